// round 13
// baseline (speedup 1.0000x reference)
#include <cuda_runtime.h>
#include <cuda_bf16.h>
#include <cstdint>

#define NV 17
#define NC 64
#define NN 128
#define NB 64
#define NT 256
#define TILE_M 64

#define KPAD 72
#define ROWB (KPAD * 2)

#define NTILES (NV * 256)            // 4352 tiles: v = tile>>8, rtile = tile&255
#define GRID 444                     // 148 SMs x 3 CTAs, single persistent wave

// A double buffer: buf b at b*BUFB; within buf: AH at 0, AL at +9216
#define BUFB (TILE_M * ROWB * 2)     // 18432
#define SM_AL_OFF (TILE_M * ROWB)    // 9216
#define SM_BIAS (2 * BUFB)           // 36864
#define SMEM_BYTES (SM_BIAS + NN * 4)

// B in fragment-direct layout: [v][n_blk(16)][ks(4)][lane(32)] of uint4{b0h,b1h,b0l,b1l}
__device__ __align__(16) uint4 g_Wfrag[NV * 16 * 4 * 32];
__device__ __align__(16) float g_bias[NN];

__device__ __forceinline__ uint32_t smem_u32(const void* p) {
    uint32_t a;
    asm("{ .reg .u64 t; cvta.to.shared.u64 t, %1; cvt.u32.u64 %0, t; }" : "=r"(a) : "l"(p));
    return a;
}
__device__ __forceinline__ void split_bf16(float x, unsigned short& h, unsigned short& l) {
    __nv_bfloat16 hb = __float2bfloat16(x);
    h = *(unsigned short*)&hb;
    float r = x - __bfloat162float(hb);
    __nv_bfloat16 lb = __float2bfloat16(r);
    l = *(unsigned short*)&lb;
}
__device__ __forceinline__ void ldsm_x4(uint32_t* r, uint32_t addr) {
    asm volatile("ldmatrix.sync.aligned.m8n8.x4.shared.b16 {%0,%1,%2,%3}, [%4];"
        : "=r"(r[0]), "=r"(r[1]), "=r"(r[2]), "=r"(r[3]) : "r"(addr));
}
__device__ __forceinline__ void mma_bf16(float* c, const uint32_t* a, const uint32_t* b) {
    asm volatile(
        "mma.sync.aligned.m16n8k16.row.col.f32.bf16.bf16.f32 "
        "{%0,%1,%2,%3}, {%4,%5,%6,%7}, {%8,%9}, {%0,%1,%2,%3};"
        : "+f"(c[0]), "+f"(c[1]), "+f"(c[2]), "+f"(c[3])
        : "r"(a[0]), "r"(a[1]), "r"(a[2]), "r"(a[3]), "r"(b[0]), "r"(b[1]));
}
__device__ __forceinline__ uint32_t packhl(unsigned short a, unsigned short b) {
    return (uint32_t)a | ((uint32_t)b << 16);
}

// ---------------------------------------------------------------------------
// Prep (unchanged from R12): grid (NV,4), softmax + BN fold, fragment-layout W.
// ---------------------------------------------------------------------------
__global__ void prep_kernel(const float* __restrict__ mat,
                            const float* __restrict__ amask,
                            const float* __restrict__ kern,
                            const float* __restrict__ gamma,
                            const float* __restrict__ beta,
                            const float* __restrict__ mean,
                            const float* __restrict__ var)
{
    const int v = blockIdx.x;
    const int ks = blockIdx.y;
    const int tid = threadIdx.x;
    const int lane = tid & 31, w = tid >> 5;
    __shared__ float aacc[4][NN];

    #pragma unroll
    for (int q = 0; q < 4; q++) aacc[q][tid] = 0.f;
    __syncthreads();

    #pragma unroll
    for (int r = 0; r < 5; r++) {
        const int m = w + r * 4;
        if (m < NV) {
            const float mt = __ldg(&mat[m * NV + v]);
            float z[4];
            #pragma unroll
            for (int j = 0; j < 4; j++)
                z[j] = mt * __ldg(&amask[(m * NV + v) * NN + lane + j * 32]);
            float mx = fmaxf(fmaxf(z[0], z[1]), fmaxf(z[2], z[3]));
            #pragma unroll
            for (int o = 16; o > 0; o >>= 1)
                mx = fmaxf(mx, __shfl_xor_sync(0xffffffffu, mx, o));
            float e[4]; float s = 0.f;
            #pragma unroll
            for (int j = 0; j < 4; j++) { e[j] = expf(z[j] - mx); s += e[j]; }
            #pragma unroll
            for (int o = 16; o > 0; o >>= 1)
                s += __shfl_xor_sync(0xffffffffu, s, o);
            const float inv = 1.f / s;
            #pragma unroll
            for (int j = 0; j < 4; j++)
                aacc[w][lane + j * 32] += e[j] * inv;
        }
    }
    __syncthreads();

    const int n = tid;
    const float scale = gamma[n] * rsqrtf(var[n] + 1e-3f);
    const float an = (aacc[0][n] + aacc[1][n] + aacc[2][n] + aacc[3][n]) * scale;

    uint4* dst = g_Wfrag + ((size_t)v * 16 + (n >> 3)) * 4 * 32 + (n & 7) * 4 + ks * 32;
    float wv[16];
    #pragma unroll
    for (int i = 0; i < 16; i++)
        wv[i] = __ldg(&kern[(v * NC + ks * 16 + i) * NN + n]) * an;
    unsigned short h[16], l[16];
    #pragma unroll
    for (int i = 0; i < 16; i++) split_bf16(wv[i], h[i], l[i]);
    #pragma unroll
    for (int q = 0; q < 4; q++) {
        uint4 u;
        u.x = packhl(h[q*2],   h[q*2+1]);
        u.y = packhl(h[q*2+8], h[q*2+9]);
        u.z = packhl(l[q*2],   l[q*2+1]);
        u.w = packhl(l[q*2+8], l[q*2+9]);
        dst[q] = u;
    }
    if (v == 0 && ks == 0) g_bias[n] = beta[n] - mean[n] * scale;
}

// --- helpers for pipelined A fill (128 threads; chunk h covers i = h*4..h*4+3) ---
__device__ __forceinline__ void fill_load(const float* __restrict__ x, int tile,
                                          int tid, int h, float4* ra, float4* rb)
{
    const int v = tile >> 8;
    const int r0 = (tile & 255) * TILE_M;
    #pragma unroll
    for (int ii = 0; ii < 4; ii++) {
        const int c = tid + 128 * (h * 4 + ii);
        const int m = c >> 4;
        const int ch = c & 15;
        const int r = r0 + m;
        const int b = r >> 8, t = r & 255;
        const float* p0 = x + (((size_t)(b * 2) * NT + t) * NV + v) * NC + ch * 4;
        ra[ii] = *(const float4*)p0;
        rb[ii] = *(const float4*)(p0 + (size_t)NT * NV * NC);
    }
}
__device__ __forceinline__ void fill_store(char* buf, int tid, int h,
                                           const float4* ra, const float4* rb)
{
    #pragma unroll
    for (int ii = 0; ii < 4; ii++) {
        const int c = tid + 128 * (h * 4 + ii);
        const int m = c >> 4;
        const int ch = c & 15;
        float y0 = ra[ii].x + rb[ii].x, y1 = ra[ii].y + rb[ii].y;
        float y2 = ra[ii].z + rb[ii].z, y3 = ra[ii].w + rb[ii].w;
        uint32_t u0 = __float_as_uint(y0), u1 = __float_as_uint(y1);
        uint32_t u2 = __float_as_uint(y2), u3 = __float_as_uint(y3);
        uint2 ph, pl;
        ph.x = __byte_perm(u0, u1, 0x7632);
        ph.y = __byte_perm(u2, u3, 0x7632);
        float l0 = y0 - __uint_as_float(u0 & 0xFFFF0000u);
        float l1 = y1 - __uint_as_float(u1 & 0xFFFF0000u);
        float l2 = y2 - __uint_as_float(u2 & 0xFFFF0000u);
        float l3 = y3 - __uint_as_float(u3 & 0xFFFF0000u);
        __nv_bfloat162 t0 = __floats2bfloat162_rn(l0, l1);
        __nv_bfloat162 t1 = __floats2bfloat162_rn(l2, l3);
        pl.x = *(uint32_t*)&t0;
        pl.y = *(uint32_t*)&t1;
        *(uint2*)(buf + m * ROWB + ch * 8) = ph;
        *(uint2*)(buf + SM_AL_OFF + m * ROWB + ch * 8) = pl;
    }
}

// ---------------------------------------------------------------------------
// Persistent GEMM: 444 CTAs x 128 thr, grid-stride over 4352 tiles,
// double-buffered A fill pipelined against the MMA loop.
// ---------------------------------------------------------------------------
__global__ void __launch_bounds__(128, 3)
gemm_kernel(const float* __restrict__ x, float* __restrict__ out)
{
    extern __shared__ __align__(16) char smem[];
    const uint32_t sbase = smem_u32(smem);
    const int tid = threadIdx.x;
    const int wid = tid >> 5;
    const int lane = tid & 31;

    // zero K pads of BOTH buffers (never rewritten) + bias
    if (tid < TILE_M) {
        #pragma unroll
        for (int b = 0; b < 2; b++) {
            *(uint4*)(smem + b * BUFB + tid * ROWB + 128) = make_uint4(0,0,0,0);
            *(uint4*)(smem + b * BUFB + SM_AL_OFF + tid * ROWB + 128) = make_uint4(0,0,0,0);
        }
    }
    ((float*)(smem + SM_BIAS))[tid] = g_bias[tid];

    // prologue: fill buf0 with first tile
    int tile = blockIdx.x;
    {
        float4 ra[4], rb[4];
        fill_load(x, tile, tid, 0, ra, rb);
        fill_store(smem, tid, 0, ra, rb);
        fill_load(x, tile, tid, 1, ra, rb);
        fill_store(smem, tid, 1, ra, rb);
    }
    __syncthreads();

    const int warp_m = (wid & 1) * 32;
    const int warp_n = (wid >> 1) * 64;
    const uint32_t a_lane = ((lane & 7) + ((lane >> 3) & 1) * 8) * ROWB
                          + ((lane >> 4) & 1) * 16;
    const float* bs = (const float*)(smem + SM_BIAS);
    const int qrow = lane >> 2;
    const int qcol = (lane & 3) * 2;

    int p = 0;
    while (tile < NTILES) {
        const int ntile = tile + GRID;
        const bool hasnext = ntile < NTILES;
        const int v = tile >> 8;
        const int r0 = (tile & 255) * TILE_M;

        const uint32_t aBaseH = sbase + p * BUFB + warp_m * ROWB + a_lane;
        const uint32_t aBaseL = aBaseH + SM_AL_OFF;
        char* nbuf = smem + (p ^ 1) * BUFB;
        const uint4* Bf = g_Wfrag + (((size_t)v * 16 + (wid >> 1) * 8) * 4) * 32 + lane;

        float acc[2][8][4];
        #pragma unroll
        for (int i = 0; i < 2; i++)
            #pragma unroll
            for (int j = 0; j < 8; j++)
                #pragma unroll
                for (int q = 0; q < 4; q++) acc[i][j][q] = 0.f;

        // ---- pipeline: load next chunk0, MMA ks0-1, store chunk0,
        //                load next chunk1, MMA ks2-3, store chunk1 ----
        float4 ra[4], rb[4];
        if (hasnext) fill_load(x, ntile, tid, 0, ra, rb);

        #pragma unroll
        for (int ks = 0; ks < 2; ks++) {
            uint32_t ah[2][4], al[2][4];
            #pragma unroll
            for (int mb = 0; mb < 2; mb++) {
                ldsm_x4(ah[mb], aBaseH + mb * 16 * ROWB + ks * 32);
                ldsm_x4(al[mb], aBaseL + mb * 16 * ROWB + ks * 32);
            }
            #pragma unroll
            for (int nb = 0; nb < 8; nb++) {
                uint4 bu = __ldg(Bf + (nb * 4 + ks) * 32);
                #pragma unroll
                for (int mb = 0; mb < 2; mb++) {
                    mma_bf16(acc[mb][nb], ah[mb], &bu.x);
                    mma_bf16(acc[mb][nb], al[mb], &bu.x);
                    mma_bf16(acc[mb][nb], ah[mb], &bu.z);
                }
            }
        }
        if (hasnext) {
            fill_store(nbuf, tid, 0, ra, rb);
            fill_load(x, ntile, tid, 1, ra, rb);
        }
        #pragma unroll
        for (int ks = 2; ks < 4; ks++) {
            uint32_t ah[2][4], al[2][4];
            #pragma unroll
            for (int mb = 0; mb < 2; mb++) {
                ldsm_x4(ah[mb], aBaseH + mb * 16 * ROWB + ks * 32);
                ldsm_x4(al[mb], aBaseL + mb * 16 * ROWB + ks * 32);
            }
            #pragma unroll
            for (int nb = 0; nb < 8; nb++) {
                uint4 bu = __ldg(Bf + (nb * 4 + ks) * 32);
                #pragma unroll
                for (int mb = 0; mb < 2; mb++) {
                    mma_bf16(acc[mb][nb], ah[mb], &bu.x);
                    mma_bf16(acc[mb][nb], al[mb], &bu.x);
                    mma_bf16(acc[mb][nb], ah[mb], &bu.z);
                }
            }
        }
        if (hasnext) fill_store(nbuf, tid, 1, ra, rb);

        // ---- epilogue: bias + ReLU + direct store ----
        #pragma unroll
        for (int nb = 0; nb < 8; nb++) {
            const int n = warp_n + nb * 8 + qcol;
            const float2 bb = *(const float2*)(bs + n);
            #pragma unroll
            for (int mb = 0; mb < 2; mb++) {
                const int mlo = warp_m + mb * 16 + qrow;
                float* o0 = out + ((size_t)(r0 + mlo) * NV + v) * NN + n;
                float* o1 = o0 + (size_t)8 * NV * NN;
                float2 r0v, r1v;
                r0v.x = fmaxf(acc[mb][nb][0] + bb.x, 0.f);
                r0v.y = fmaxf(acc[mb][nb][1] + bb.y, 0.f);
                r1v.x = fmaxf(acc[mb][nb][2] + bb.x, 0.f);
                r1v.y = fmaxf(acc[mb][nb][3] + bb.y, 0.f);
                *(float2*)o0 = r0v;
                *(float2*)o1 = r1v;
            }
        }

        __syncthreads();
        tile = ntile;
        p ^= 1;
    }
}

extern "C" void kernel_launch(void* const* d_in, const int* in_sizes, int n_in,
                              void* d_out, int out_size)
{
    const float* inputs = (const float*)d_in[0];
    const float* mat    = (const float*)d_in[1];
    const float* amask  = (const float*)d_in[2];
    const float* kern   = (const float*)d_in[3];
    const float* gamma  = (const float*)d_in[4];
    const float* beta   = (const float*)d_in[5];
    const float* mean   = (const float*)d_in[6];
    const float* var    = (const float*)d_in[7];
    float* out = (float*)d_out;

    cudaFuncSetAttribute(gemm_kernel,
                         cudaFuncAttributeMaxDynamicSharedMemorySize,
                         SMEM_BYTES);

    prep_kernel<<<dim3(NV, 4), NN>>>(mat, amask, kern, gamma, beta, mean, var);
    gemm_kernel<<<GRID, 128, SMEM_BYTES>>>(inputs, out);
}

// round 14
// speedup vs baseline: 1.2490x; 1.2490x over previous
#include <cuda_runtime.h>
#include <cuda_fp16.h>
#include <cstdint>

#define NV 17
#define NC 64
#define NN 128
#define NB 64
#define NT 256
#define TILE_M 64

#define KPAD 72                       // A rows: 64 fp16 + 8 pad -> 144B, LDSM conflict-free
#define ROWB (KPAD * 2)

// smem byte offsets (A tiles + bias only; B never touches smem)
#define SM_AH 0
#define SM_AL (SM_AH + TILE_M * ROWB)       // 9216
#define SM_BIAS (SM_AL + TILE_M * ROWB)     // 18432
#define SMEM_BYTES (SM_BIAS + NN * 4)       // 18944

// B in fragment-direct layout: [v][n_blk(16)][ks(4)][lane(32)] of uint2{b0,b1} fp16x2
__device__ __align__(16) uint2 g_Wfrag[NV * 16 * 4 * 32];
__device__ __align__(16) float g_bias[NN];

__device__ __forceinline__ uint32_t smem_u32(const void* p) {
    uint32_t a;
    asm("{ .reg .u64 t; cvta.to.shared.u64 t, %1; cvt.u32.u64 %0, t; }" : "=r"(a) : "l"(p));
    return a;
}
__device__ __forceinline__ void ldsm_x4(uint32_t* r, uint32_t addr) {
    asm volatile("ldmatrix.sync.aligned.m8n8.x4.shared.b16 {%0,%1,%2,%3}, [%4];"
        : "=r"(r[0]), "=r"(r[1]), "=r"(r[2]), "=r"(r[3]) : "r"(addr));
}
__device__ __forceinline__ void mma_fp16(float* c, const uint32_t* a, const uint32_t* b) {
    asm volatile(
        "mma.sync.aligned.m16n8k16.row.col.f32.f16.f16.f32 "
        "{%0,%1,%2,%3}, {%4,%5,%6,%7}, {%8,%9}, {%0,%1,%2,%3};"
        : "+f"(c[0]), "+f"(c[1]), "+f"(c[2]), "+f"(c[3])
        : "r"(a[0]), "r"(a[1]), "r"(a[2]), "r"(a[3]), "r"(b[0]), "r"(b[1]));
}
__device__ __forceinline__ uint32_t packh(__half a, __half b) {
    __half2 h2 = __halves2half2(a, b);
    return *(uint32_t*)&h2;
}

// ---------------------------------------------------------------------------
// Prep: grid (NV, 4) — block (v, ks). Warp-parallel softmax (redundant per ks,
// cheap), then emit the ks-chunk of W'[v] as single rn-fp16 fragments, BN folded.
// ---------------------------------------------------------------------------
__global__ void prep_kernel(const float* __restrict__ mat,
                            const float* __restrict__ amask,
                            const float* __restrict__ kern,
                            const float* __restrict__ gamma,
                            const float* __restrict__ beta,
                            const float* __restrict__ mean,
                            const float* __restrict__ var)
{
    const int v = blockIdx.x;
    const int ks = blockIdx.y;            // 0..3
    const int tid = threadIdx.x;          // 0..127
    const int lane = tid & 31, w = tid >> 5;
    __shared__ float aacc[4][NN];

    #pragma unroll
    for (int q = 0; q < 4; q++) aacc[q][tid] = 0.f;
    __syncthreads();

    #pragma unroll
    for (int r = 0; r < 5; r++) {
        const int m = w + r * 4;
        if (m < NV) {
            const float mt = __ldg(&mat[m * NV + v]);
            float z[4];
            #pragma unroll
            for (int j = 0; j < 4; j++)
                z[j] = mt * __ldg(&amask[(m * NV + v) * NN + lane + j * 32]);
            float mx = fmaxf(fmaxf(z[0], z[1]), fmaxf(z[2], z[3]));
            #pragma unroll
            for (int o = 16; o > 0; o >>= 1)
                mx = fmaxf(mx, __shfl_xor_sync(0xffffffffu, mx, o));
            float e[4]; float s = 0.f;
            #pragma unroll
            for (int j = 0; j < 4; j++) { e[j] = expf(z[j] - mx); s += e[j]; }
            #pragma unroll
            for (int o = 16; o > 0; o >>= 1)
                s += __shfl_xor_sync(0xffffffffu, s, o);
            const float inv = 1.f / s;
            #pragma unroll
            for (int j = 0; j < 4; j++)
                aacc[w][lane + j * 32] += e[j] * inv;
        }
    }
    __syncthreads();

    const int n = tid;
    const float scale = gamma[n] * rsqrtf(var[n] + 1e-3f);
    const float an = (aacc[0][n] + aacc[1][n] + aacc[2][n] + aacc[3][n]) * scale;

    // fragments: lane l of n_blk holds rows n = n_blk*8 + l>>2,
    // k-pairs (l&3)*2 (+1), b1 at k+8; ks selects 16-wide k chunk.
    uint2* dst = g_Wfrag + ((size_t)v * 16 + (n >> 3)) * 4 * 32 + (n & 7) * 4 + ks * 32;
    float wv[16];
    #pragma unroll
    for (int i = 0; i < 16; i++)
        wv[i] = __ldg(&kern[(v * NC + ks * 16 + i) * NN + n]) * an;
    __half h[16];
    #pragma unroll
    for (int i = 0; i < 16; i++) h[i] = __float2half_rn(wv[i]);
    #pragma unroll
    for (int q = 0; q < 4; q++) {
        uint2 u;
        u.x = packh(h[q*2],   h[q*2+1]);      // b0 (k, k+1)
        u.y = packh(h[q*2+8], h[q*2+9]);      // b1 (k+8, k+9)
        dst[q] = u;
    }
    if (v == 0 && ks == 0) g_bias[n] = beta[n] - mean[n] * scale;
}

// ---------------------------------------------------------------------------
// GEMM: CTA 64m x 128n for one v, K=64. 4 warps (2m x 2n), warp tile 32m x 64n.
// A split fp16 hi/lo (2-product fp32 emulation), B single fp16 fragment from L2.
// 4 CTAs/SM, direct STG epilogue.
// ---------------------------------------------------------------------------
__global__ void __launch_bounds__(128, 4)
gemm_kernel(const float* __restrict__ x, float* __restrict__ out)
{
    extern __shared__ __align__(16) char smem[];
    const uint32_t sbase = smem_u32(smem);
    const int tid = threadIdx.x;
    const int wid = tid >> 5;              // 0..3
    const int lane = tid & 31;
    const int v = blockIdx.y;
    const int r0 = blockIdx.x * TILE_M;

    // --- Fill A tile, fully coalesced; fp16 split: ah=f16(y), al=f16(y-ah) ---
    #pragma unroll
    for (int i = 0; i < 8; i++) {
        const int c = tid + 128 * i;          // 0..1023
        const int m = c >> 4;
        const int ch = c & 15;
        const int r = r0 + m;
        const int b = r >> 8, t = r & 255;    // T = 256
        const float* p0 = x + (((size_t)(b * 2) * NT + t) * NV + v) * NC + ch * 4;
        float4 a0 = *(const float4*)p0;
        float4 a1 = *(const float4*)(p0 + (size_t)NT * NV * NC);
        float y0 = a0.x + a1.x, y1 = a0.y + a1.y;
        float y2 = a0.z + a1.z, y3 = a0.w + a1.w;
        __half2 h01 = __floats2half2_rn(y0, y1);
        __half2 h23 = __floats2half2_rn(y2, y3);
        float2 f01 = __half22float2(h01);
        float2 f23 = __half22float2(h23);
        __half2 l01 = __floats2half2_rn(y0 - f01.x, y1 - f01.y);
        __half2 l23 = __floats2half2_rn(y2 - f23.x, y3 - f23.y);
        uint2 ph, pl;
        ph.x = *(uint32_t*)&h01; ph.y = *(uint32_t*)&h23;
        pl.x = *(uint32_t*)&l01; pl.y = *(uint32_t*)&l23;
        *(uint2*)(smem + SM_AH + m * ROWB + ch * 8) = ph;
        *(uint2*)(smem + SM_AL + m * ROWB + ch * 8) = pl;
    }
    // zero K pad (bytes 128..143 of each row) + bias
    if (tid < TILE_M) {
        *(uint4*)(smem + SM_AH + tid * ROWB + 128) = make_uint4(0,0,0,0);
        *(uint4*)(smem + SM_AL + tid * ROWB + 128) = make_uint4(0,0,0,0);
    }
    ((float*)(smem + SM_BIAS))[tid] = g_bias[tid];
    __syncthreads();

    const int warp_m = (wid & 1) * 32;      // 2 m-groups
    const int warp_n = (wid >> 1) * 64;     // 2 n-groups (64 n each)

    const uint32_t a_lane = ((lane & 7) + ((lane >> 3) & 1) * 8) * ROWB
                          + ((lane >> 4) & 1) * 16;

    float acc[2][8][4];
    #pragma unroll
    for (int i = 0; i < 2; i++)
        #pragma unroll
        for (int j = 0; j < 8; j++)
            #pragma unroll
            for (int q = 0; q < 4; q++) acc[i][j][q] = 0.f;

    const uint32_t aBaseH = sbase + SM_AH + warp_m * ROWB + a_lane;
    const uint32_t aBaseL = sbase + SM_AL + warp_m * ROWB + a_lane;
    // this warp's 8 n_blks start at (wid>>1)*8
    const uint2* Bf = g_Wfrag + (((size_t)v * 16 + (wid >> 1) * 8) * 4) * 32 + lane;

    #pragma unroll
    for (int ks = 0; ks < 4; ks++) {
        uint32_t ah[2][4], al[2][4];
        #pragma unroll
        for (int mb = 0; mb < 2; mb++) {
            ldsm_x4(ah[mb], aBaseH + mb * 16 * ROWB + ks * 32);
            ldsm_x4(al[mb], aBaseL + mb * 16 * ROWB + ks * 32);
        }
        #pragma unroll
        for (int nb = 0; nb < 8; nb++) {
            uint2 bu = __ldg(Bf + (nb * 4 + ks) * 32);
            #pragma unroll
            for (int mb = 0; mb < 2; mb++) {
                mma_fp16(acc[mb][nb], ah[mb], &bu.x);
                mma_fp16(acc[mb][nb], al[mb], &bu.x);
            }
        }
    }

    // --- Epilogue: bias + ReLU + direct store (bias hoisted per nb) ---
    const float* bs = (const float*)(smem + SM_BIAS);
    const int qrow = lane >> 2;
    const int qcol = (lane & 3) * 2;
    #pragma unroll
    for (int nb = 0; nb < 8; nb++) {
        const int n = warp_n + nb * 8 + qcol;
        const float2 bb = *(const float2*)(bs + n);
        #pragma unroll
        for (int mb = 0; mb < 2; mb++) {
            const int mlo = warp_m + mb * 16 + qrow;
            float* o0 = out + ((size_t)(r0 + mlo) * NV + v) * NN + n;
            float* o1 = o0 + (size_t)8 * NV * NN;
            float2 r0v, r1v;
            r0v.x = fmaxf(acc[mb][nb][0] + bb.x, 0.f);
            r0v.y = fmaxf(acc[mb][nb][1] + bb.y, 0.f);
            r1v.x = fmaxf(acc[mb][nb][2] + bb.x, 0.f);
            r1v.y = fmaxf(acc[mb][nb][3] + bb.y, 0.f);
            *(float2*)o0 = r0v;
            *(float2*)o1 = r1v;
        }
    }
}

extern "C" void kernel_launch(void* const* d_in, const int* in_sizes, int n_in,
                              void* d_out, int out_size)
{
    const float* inputs = (const float*)d_in[0];
    const float* mat    = (const float*)d_in[1];
    const float* amask  = (const float*)d_in[2];
    const float* kern   = (const float*)d_in[3];
    const float* gamma  = (const float*)d_in[4];
    const float* beta   = (const float*)d_in[5];
    const float* mean   = (const float*)d_in[6];
    const float* var    = (const float*)d_in[7];
    float* out = (float*)d_out;

    cudaFuncSetAttribute(gemm_kernel,
                         cudaFuncAttributeMaxDynamicSharedMemorySize,
                         SMEM_BYTES);

    prep_kernel<<<dim3(NV, 4), NN>>>(mat, amask, kern, gamma, beta, mean, var);
    gemm_kernel<<<dim3((NB * NT) / TILE_M, NV), 128, SMEM_BYTES>>>(inputs, out);
}

// round 15
// speedup vs baseline: 1.3782x; 1.1034x over previous
#include <cuda_runtime.h>
#include <cuda_fp16.h>
#include <cstdint>

#define NV 17
#define NC 64
#define NN 128
#define NB 64
#define NT 256
#define TILE_M 64

#define KPAD 72                       // A rows: 64 fp16 + 8 pad -> 144B, LDSM conflict-free
#define ROWB (KPAD * 2)

// smem byte offsets (single A tile + bias; B never touches smem)
#define SM_AH 0
#define SM_BIAS (SM_AH + TILE_M * ROWB)     // 9216
#define SMEM_BYTES (SM_BIAS + NN * 4)       // 9728

// B in fragment-direct layout: [v][n_blk(16)][ks(4)][lane(32)] of uint2{b0,b1} fp16x2
__device__ __align__(16) uint2 g_Wfrag[NV * 16 * 4 * 32];
__device__ __align__(16) float g_bias[NN];

__device__ __forceinline__ uint32_t smem_u32(const void* p) {
    uint32_t a;
    asm("{ .reg .u64 t; cvta.to.shared.u64 t, %1; cvt.u32.u64 %0, t; }" : "=r"(a) : "l"(p));
    return a;
}
__device__ __forceinline__ void ldsm_x4(uint32_t* r, uint32_t addr) {
    asm volatile("ldmatrix.sync.aligned.m8n8.x4.shared.b16 {%0,%1,%2,%3}, [%4];"
        : "=r"(r[0]), "=r"(r[1]), "=r"(r[2]), "=r"(r[3]) : "r"(addr));
}
__device__ __forceinline__ void mma_fp16(float* c, const uint32_t* a, const uint32_t* b) {
    asm volatile(
        "mma.sync.aligned.m16n8k16.row.col.f32.f16.f16.f32 "
        "{%0,%1,%2,%3}, {%4,%5,%6,%7}, {%8,%9}, {%0,%1,%2,%3};"
        : "+f"(c[0]), "+f"(c[1]), "+f"(c[2]), "+f"(c[3])
        : "r"(a[0]), "r"(a[1]), "r"(a[2]), "r"(a[3]), "r"(b[0]), "r"(b[1]));
}
__device__ __forceinline__ uint32_t packh(__half a, __half b) {
    __half2 h2 = __halves2half2(a, b);
    return *(uint32_t*)&h2;
}

// ---------------------------------------------------------------------------
// Prep: grid (NV, 4) — block (v, ks). Warp-parallel softmax (redundant per ks,
// cheap), then emit the ks-chunk of W'[v] as single rn-fp16 fragments, BN folded.
// ---------------------------------------------------------------------------
__global__ void prep_kernel(const float* __restrict__ mat,
                            const float* __restrict__ amask,
                            const float* __restrict__ kern,
                            const float* __restrict__ gamma,
                            const float* __restrict__ beta,
                            const float* __restrict__ mean,
                            const float* __restrict__ var)
{
    const int v = blockIdx.x;
    const int ks = blockIdx.y;            // 0..3
    const int tid = threadIdx.x;          // 0..127
    const int lane = tid & 31, w = tid >> 5;
    __shared__ float aacc[4][NN];

    #pragma unroll
    for (int q = 0; q < 4; q++) aacc[q][tid] = 0.f;
    __syncthreads();

    #pragma unroll
    for (int r = 0; r < 5; r++) {
        const int m = w + r * 4;
        if (m < NV) {
            const float mt = __ldg(&mat[m * NV + v]);
            float z[4];
            #pragma unroll
            for (int j = 0; j < 4; j++)
                z[j] = mt * __ldg(&amask[(m * NV + v) * NN + lane + j * 32]);
            float mx = fmaxf(fmaxf(z[0], z[1]), fmaxf(z[2], z[3]));
            #pragma unroll
            for (int o = 16; o > 0; o >>= 1)
                mx = fmaxf(mx, __shfl_xor_sync(0xffffffffu, mx, o));
            float e[4]; float s = 0.f;
            #pragma unroll
            for (int j = 0; j < 4; j++) { e[j] = expf(z[j] - mx); s += e[j]; }
            #pragma unroll
            for (int o = 16; o > 0; o >>= 1)
                s += __shfl_xor_sync(0xffffffffu, s, o);
            const float inv = 1.f / s;
            #pragma unroll
            for (int j = 0; j < 4; j++)
                aacc[w][lane + j * 32] += e[j] * inv;
        }
    }
    __syncthreads();

    const int n = tid;
    const float scale = gamma[n] * rsqrtf(var[n] + 1e-3f);
    const float an = (aacc[0][n] + aacc[1][n] + aacc[2][n] + aacc[3][n]) * scale;

    // fragments: lane l of n_blk holds rows n = n_blk*8 + l>>2,
    // k-pairs (l&3)*2 (+1), b1 at k+8; ks selects 16-wide k chunk.
    uint2* dst = g_Wfrag + ((size_t)v * 16 + (n >> 3)) * 4 * 32 + (n & 7) * 4 + ks * 32;
    float wv[16];
    #pragma unroll
    for (int i = 0; i < 16; i++)
        wv[i] = __ldg(&kern[(v * NC + ks * 16 + i) * NN + n]) * an;
    __half h[16];
    #pragma unroll
    for (int i = 0; i < 16; i++) h[i] = __float2half_rn(wv[i]);
    #pragma unroll
    for (int q = 0; q < 4; q++) {
        uint2 u;
        u.x = packh(h[q*2],   h[q*2+1]);      // b0 (k, k+1)
        u.y = packh(h[q*2+8], h[q*2+9]);      // b1 (k+8, k+9)
        dst[q] = u;
    }
    if (v == 0 && ks == 0) g_bias[n] = beta[n] - mean[n] * scale;
}

// ---------------------------------------------------------------------------
// GEMM: CTA 64m x 128n for one v, K=64. 4 warps (2m x 2n), warp tile 32m x 64n.
// A single fp16 (rn), B single fp16 fragment from L2. 4 CTAs/SM, direct STG.
// ---------------------------------------------------------------------------
__global__ void __launch_bounds__(128, 4)
gemm_kernel(const float* __restrict__ x, float* __restrict__ out)
{
    extern __shared__ __align__(16) char smem[];
    const uint32_t sbase = smem_u32(smem);
    const int tid = threadIdx.x;
    const int wid = tid >> 5;              // 0..3
    const int lane = tid & 31;
    const int v = blockIdx.y;
    const int r0 = blockIdx.x * TILE_M;

    // --- Fill A tile, fully coalesced; single rn-fp16 ---
    #pragma unroll
    for (int i = 0; i < 8; i++) {
        const int c = tid + 128 * i;          // 0..1023
        const int m = c >> 4;
        const int ch = c & 15;
        const int r = r0 + m;
        const int b = r >> 8, t = r & 255;    // T = 256
        const float* p0 = x + (((size_t)(b * 2) * NT + t) * NV + v) * NC + ch * 4;
        float4 a0 = *(const float4*)p0;
        float4 a1 = *(const float4*)(p0 + (size_t)NT * NV * NC);
        __half2 h01 = __floats2half2_rn(a0.x + a1.x, a0.y + a1.y);
        __half2 h23 = __floats2half2_rn(a0.z + a1.z, a0.w + a1.w);
        uint2 ph;
        ph.x = *(uint32_t*)&h01; ph.y = *(uint32_t*)&h23;
        *(uint2*)(smem + SM_AH + m * ROWB + ch * 8) = ph;
    }
    // zero K pad (bytes 128..143 of each row) + bias
    if (tid < TILE_M)
        *(uint4*)(smem + SM_AH + tid * ROWB + 128) = make_uint4(0,0,0,0);
    ((float*)(smem + SM_BIAS))[tid] = g_bias[tid];
    __syncthreads();

    const int warp_m = (wid & 1) * 32;      // 2 m-groups
    const int warp_n = (wid >> 1) * 64;     // 2 n-groups (64 n each)

    const uint32_t a_lane = ((lane & 7) + ((lane >> 3) & 1) * 8) * ROWB
                          + ((lane >> 4) & 1) * 16;

    float acc[2][8][4];
    #pragma unroll
    for (int i = 0; i < 2; i++)
        #pragma unroll
        for (int j = 0; j < 8; j++)
            #pragma unroll
            for (int q = 0; q < 4; q++) acc[i][j][q] = 0.f;

    const uint32_t aBaseH = sbase + SM_AH + warp_m * ROWB + a_lane;
    // this warp's 8 n_blks start at (wid>>1)*8
    const uint2* Bf = g_Wfrag + (((size_t)v * 16 + (wid >> 1) * 8) * 4) * 32 + lane;

    #pragma unroll
    for (int ks = 0; ks < 4; ks++) {
        uint32_t ah[2][4];
        #pragma unroll
        for (int mb = 0; mb < 2; mb++)
            ldsm_x4(ah[mb], aBaseH + mb * 16 * ROWB + ks * 32);
        #pragma unroll
        for (int nb = 0; nb < 8; nb++) {
            uint2 bu = __ldg(Bf + (nb * 4 + ks) * 32);
            #pragma unroll
            for (int mb = 0; mb < 2; mb++)
                mma_fp16(acc[mb][nb], ah[mb], &bu.x);
        }
    }

    // --- Epilogue: bias + ReLU + direct store (bias hoisted per nb) ---
    const float* bs = (const float*)(smem + SM_BIAS);
    const int qrow = lane >> 2;
    const int qcol = (lane & 3) * 2;
    #pragma unroll
    for (int nb = 0; nb < 8; nb++) {
        const int n = warp_n + nb * 8 + qcol;
        const float2 bb = *(const float2*)(bs + n);
        #pragma unroll
        for (int mb = 0; mb < 2; mb++) {
            const int mlo = warp_m + mb * 16 + qrow;
            float* o0 = out + ((size_t)(r0 + mlo) * NV + v) * NN + n;
            float* o1 = o0 + (size_t)8 * NV * NN;
            float2 r0v, r1v;
            r0v.x = fmaxf(acc[mb][nb][0] + bb.x, 0.f);
            r0v.y = fmaxf(acc[mb][nb][1] + bb.y, 0.f);
            r1v.x = fmaxf(acc[mb][nb][2] + bb.x, 0.f);
            r1v.y = fmaxf(acc[mb][nb][3] + bb.y, 0.f);
            *(float2*)o0 = r0v;
            *(float2*)o1 = r1v;
        }
    }
}

extern "C" void kernel_launch(void* const* d_in, const int* in_sizes, int n_in,
                              void* d_out, int out_size)
{
    const float* inputs = (const float*)d_in[0];
    const float* mat    = (const float*)d_in[1];
    const float* amask  = (const float*)d_in[2];
    const float* kern   = (const float*)d_in[3];
    const float* gamma  = (const float*)d_in[4];
    const float* beta   = (const float*)d_in[5];
    const float* mean   = (const float*)d_in[6];
    const float* var    = (const float*)d_in[7];
    float* out = (float*)d_out;

    cudaFuncSetAttribute(gemm_kernel,
                         cudaFuncAttributeMaxDynamicSharedMemorySize,
                         SMEM_BYTES);

    prep_kernel<<<dim3(NV, 4), NN>>>(mat, amask, kern, gamma, beta, mean, var);
    gemm_kernel<<<dim3((NB * NT) / TILE_M, NV), 128, SMEM_BYTES>>>(inputs, out);
}

// round 16
// speedup vs baseline: 1.4275x; 1.0357x over previous
#include <cuda_runtime.h>
#include <cuda_fp16.h>
#include <cstdint>

#define NV 17
#define NC 64
#define NN 128
#define NB 64
#define NT 256
#define TILE_M 64

#define KPAD 72                       // A rows: 64 fp16 + 8 pad -> 144B, LDSM conflict-free
#define ROWB (KPAD * 2)

// smem byte offsets (single A tile + bias; B never touches smem)
#define SM_AH 0
#define SM_BIAS (SM_AH + TILE_M * ROWB)     // 9216
#define SMEM_BYTES (SM_BIAS + NN * 4)       // 9728

// B in fragment-direct layout: [v][n_blk(16)][ks(4)][lane(32)] of uint2{b0,b1} fp16x2
__device__ __align__(16) uint2 g_Wfrag[NV * 16 * 4 * 32];
__device__ __align__(16) float g_bias[NN];

__device__ __forceinline__ uint32_t smem_u32(const void* p) {
    uint32_t a;
    asm("{ .reg .u64 t; cvta.to.shared.u64 t, %1; cvt.u32.u64 %0, t; }" : "=r"(a) : "l"(p));
    return a;
}
__device__ __forceinline__ void ldsm_x4(uint32_t* r, uint32_t addr) {
    asm volatile("ldmatrix.sync.aligned.m8n8.x4.shared.b16 {%0,%1,%2,%3}, [%4];"
        : "=r"(r[0]), "=r"(r[1]), "=r"(r[2]), "=r"(r[3]) : "r"(addr));
}
__device__ __forceinline__ void mma_fp16(float* c, const uint32_t* a, const uint32_t* b) {
    asm volatile(
        "mma.sync.aligned.m16n8k16.row.col.f32.f16.f16.f32 "
        "{%0,%1,%2,%3}, {%4,%5,%6,%7}, {%8,%9}, {%0,%1,%2,%3};"
        : "+f"(c[0]), "+f"(c[1]), "+f"(c[2]), "+f"(c[3])
        : "r"(a[0]), "r"(a[1]), "r"(a[2]), "r"(a[3]), "r"(b[0]), "r"(b[1]));
}
__device__ __forceinline__ uint32_t packh(__half a, __half b) {
    __half2 h2 = __halves2half2(a, b);
    return *(uint32_t*)&h2;
}

// ---------------------------------------------------------------------------
// Prep: grid (NV, 4) — block (v, ks). All loads batched upfront; softmax
// without max-subtraction (|z| <= ~1, shift-invariant). Emits fp16 fragments.
// ---------------------------------------------------------------------------
__global__ void prep_kernel(const float* __restrict__ mat,
                            const float* __restrict__ amask,
                            const float* __restrict__ kern,
                            const float* __restrict__ gamma,
                            const float* __restrict__ beta,
                            const float* __restrict__ mean,
                            const float* __restrict__ var)
{
    const int v = blockIdx.x;
    const int ks = blockIdx.y;            // 0..3
    const int tid = threadIdx.x;          // 0..127
    const int lane = tid & 31, w = tid >> 5;
    __shared__ float aacc[4][NN];

    // batch-load all inputs for this warp's 5 m-rows (independent LDGs)
    float mt[5];
    float za[5][4];
    #pragma unroll
    for (int r = 0; r < 5; r++) {
        const int m = w + r * 4;
        const bool ok = m < NV;
        mt[r] = ok ? __ldg(&mat[m * NV + v]) : 0.f;
        #pragma unroll
        for (int j = 0; j < 4; j++)
            za[r][j] = ok ? __ldg(&amask[(m * NV + v) * NN + lane + j * 32]) : 0.f;
    }
    // batch-load the kern chunk too (overlaps with softmax below)
    float wv[16];
    #pragma unroll
    for (int i = 0; i < 16; i++)
        wv[i] = __ldg(&kern[(v * NC + ks * 16 + i) * NN + tid]);

    // softmax over n (no max-sub), accumulate a[n] contribution per warp
    float acc = 0.f;
    #pragma unroll
    for (int r = 0; r < 5; r++) {
        const int m = w + r * 4;
        if (m < NV) {
            float e[4]; float s = 0.f;
            #pragma unroll
            for (int j = 0; j < 4; j++) { e[j] = expf(mt[r] * za[r][j]); s += e[j]; }
            #pragma unroll
            for (int o = 16; o > 0; o >>= 1)
                s += __shfl_xor_sync(0xffffffffu, s, o);
            const float inv = 1.f / s;
            // this lane's 4 n-values: lane + j*32 — accumulate into per-warp buf later
            #pragma unroll
            for (int j = 0; j < 4; j++) e[j] *= inv;
            // stash into za to reuse registers
            #pragma unroll
            for (int j = 0; j < 4; j++) za[r][j] = e[j];
        } else {
            #pragma unroll
            for (int j = 0; j < 4; j++) za[r][j] = 0.f;
        }
    }
    // per-warp partial a[n]: sum of its 5 rows
    #pragma unroll
    for (int j = 0; j < 4; j++) {
        float p = za[0][j] + za[1][j] + za[2][j] + za[3][j] + za[4][j];
        aacc[w][lane + j * 32] = p;
    }
    __syncthreads();

    const int n = tid;
    const float scale = gamma[n] * rsqrtf(var[n] + 1e-3f);
    const float an = (aacc[0][n] + aacc[1][n] + aacc[2][n] + aacc[3][n]) * scale;

    // fragments: lane l of n_blk holds rows n = n_blk*8 + l>>2,
    // k-pairs (l&3)*2 (+1), b1 at k+8; ks selects 16-wide k chunk.
    uint2* dst = g_Wfrag + ((size_t)v * 16 + (n >> 3)) * 4 * 32 + (n & 7) * 4 + ks * 32;
    __half h[16];
    #pragma unroll
    for (int i = 0; i < 16; i++) h[i] = __float2half_rn(wv[i] * an);
    #pragma unroll
    for (int q = 0; q < 4; q++) {
        uint2 u;
        u.x = packh(h[q*2],   h[q*2+1]);      // b0 (k, k+1)
        u.y = packh(h[q*2+8], h[q*2+9]);      // b1 (k+8, k+9)
        dst[q] = u;
    }
    if (v == 0 && ks == 0) g_bias[n] = beta[n] - mean[n] * scale;
}

// ---------------------------------------------------------------------------
// GEMM: CTA 64m x 128n for one v, K=64. 4 warps (2m x 2n), warp tile 32m x 64n.
// A single fp16 (rn), B fragments double-buffered across ks. 4 CTAs/SM.
// ---------------------------------------------------------------------------
__global__ void __launch_bounds__(128, 4)
gemm_kernel(const float* __restrict__ x, float* __restrict__ out)
{
    extern __shared__ __align__(16) char smem[];
    const uint32_t sbase = smem_u32(smem);
    const int tid = threadIdx.x;
    const int wid = tid >> 5;              // 0..3
    const int lane = tid & 31;
    const int v = blockIdx.y;
    const int r0 = blockIdx.x * TILE_M;

    // --- Fill A tile, fully coalesced; single rn-fp16 ---
    #pragma unroll
    for (int i = 0; i < 8; i++) {
        const int c = tid + 128 * i;          // 0..1023
        const int m = c >> 4;
        const int ch = c & 15;
        const int r = r0 + m;
        const int b = r >> 8, t = r & 255;    // T = 256
        const float* p0 = x + (((size_t)(b * 2) * NT + t) * NV + v) * NC + ch * 4;
        float4 a0 = *(const float4*)p0;
        float4 a1 = *(const float4*)(p0 + (size_t)NT * NV * NC);
        __half2 h01 = __floats2half2_rn(a0.x + a1.x, a0.y + a1.y);
        __half2 h23 = __floats2half2_rn(a0.z + a1.z, a0.w + a1.w);
        uint2 ph;
        ph.x = *(uint32_t*)&h01; ph.y = *(uint32_t*)&h23;
        *(uint2*)(smem + SM_AH + m * ROWB + ch * 8) = ph;
    }
    // zero K pad (bytes 128..143 of each row) + bias
    if (tid < TILE_M)
        *(uint4*)(smem + SM_AH + tid * ROWB + 128) = make_uint4(0,0,0,0);
    ((float*)(smem + SM_BIAS))[tid] = g_bias[tid];

    const int warp_m = (wid & 1) * 32;      // 2 m-groups
    const int warp_n = (wid >> 1) * 64;     // 2 n-groups (64 n each)
    const uint32_t a_lane = ((lane & 7) + ((lane >> 3) & 1) * 8) * ROWB
                          + ((lane >> 4) & 1) * 16;
    const uint32_t aBaseH = sbase + SM_AH + warp_m * ROWB + a_lane;
    const uint2* Bf = g_Wfrag + (((size_t)v * 16 + (wid >> 1) * 8) * 4) * 32 + lane;

    // prefetch B for ks=0 (before the barrier — independent of smem)
    uint2 bcur[8];
    #pragma unroll
    for (int nb = 0; nb < 8; nb++) bcur[nb] = __ldg(Bf + (nb * 4 + 0) * 32);

    float acc[2][8][4];
    #pragma unroll
    for (int i = 0; i < 2; i++)
        #pragma unroll
        for (int j = 0; j < 8; j++)
            #pragma unroll
            for (int q = 0; q < 4; q++) acc[i][j][q] = 0.f;

    __syncthreads();

    #pragma unroll
    for (int ks = 0; ks < 4; ks++) {
        uint2 bnext[8];
        if (ks < 3) {
            #pragma unroll
            for (int nb = 0; nb < 8; nb++)
                bnext[nb] = __ldg(Bf + (nb * 4 + ks + 1) * 32);
        }
        uint32_t ah[2][4];
        #pragma unroll
        for (int mb = 0; mb < 2; mb++)
            ldsm_x4(ah[mb], aBaseH + mb * 16 * ROWB + ks * 32);
        #pragma unroll
        for (int nb = 0; nb < 8; nb++) {
            #pragma unroll
            for (int mb = 0; mb < 2; mb++)
                mma_fp16(acc[mb][nb], ah[mb], &bcur[nb].x);
        }
        if (ks < 3) {
            #pragma unroll
            for (int nb = 0; nb < 8; nb++) bcur[nb] = bnext[nb];
        }
    }

    // --- Epilogue: bias + ReLU + direct store (bias hoisted per nb) ---
    const float* bs = (const float*)(smem + SM_BIAS);
    const int qrow = lane >> 2;
    const int qcol = (lane & 3) * 2;
    #pragma unroll
    for (int nb = 0; nb < 8; nb++) {
        const int n = warp_n + nb * 8 + qcol;
        const float2 bb = *(const float2*)(bs + n);
        #pragma unroll
        for (int mb = 0; mb < 2; mb++) {
            const int mlo = warp_m + mb * 16 + qrow;
            float* o0 = out + ((size_t)(r0 + mlo) * NV + v) * NN + n;
            float* o1 = o0 + (size_t)8 * NV * NN;
            float2 r0v, r1v;
            r0v.x = fmaxf(acc[mb][nb][0] + bb.x, 0.f);
            r0v.y = fmaxf(acc[mb][nb][1] + bb.y, 0.f);
            r1v.x = fmaxf(acc[mb][nb][2] + bb.x, 0.f);
            r1v.y = fmaxf(acc[mb][nb][3] + bb.y, 0.f);
            *(float2*)o0 = r0v;
            *(float2*)o1 = r1v;
        }
    }
}

extern "C" void kernel_launch(void* const* d_in, const int* in_sizes, int n_in,
                              void* d_out, int out_size)
{
    const float* inputs = (const float*)d_in[0];
    const float* mat    = (const float*)d_in[1];
    const float* amask  = (const float*)d_in[2];
    const float* kern   = (const float*)d_in[3];
    const float* gamma  = (const float*)d_in[4];
    const float* beta   = (const float*)d_in[5];
    const float* mean   = (const float*)d_in[6];
    const float* var    = (const float*)d_in[7];
    float* out = (float*)d_out;

    cudaFuncSetAttribute(gemm_kernel,
                         cudaFuncAttributeMaxDynamicSharedMemorySize,
                         SMEM_BYTES);

    prep_kernel<<<dim3(NV, 4), NN>>>(mat, amask, kern, gamma, beta, mean, var);
    gemm_kernel<<<dim3((NB * NT) / TILE_M, NV), 128, SMEM_BYTES>>>(inputs, out);
}